// round 11
// baseline (speedup 1.0000x reference)
#include <cuda_runtime.h>
#include <math.h>

#define NN    8192
#define NL    16
#define NE    (NN * 128)         /* 1048576 edges per layer */
#define EV    (NE / 4)           /* 262144 int4 edge-vectors */
#define NR    32                 /* global replicas for the REDG half */
#define NOUT  16
#define EOUT  (NN * NOUT)        /* 131072 output edges */

#define LGRID 296                /* 2 CTAs/SM (64 KB dyn smem each) */
#define GS    (LGRID * 512)      /* 151552: vec0 for all threads, vec1 if g+GS < EV */
#define NSLICE (LGRID + NR)      /* 328 partial arrays to fold */

// Unified partial-sum arrays: rows [0,296) = per-CTA slices (plain STG),
// rows [296,328) = replicated global accumulators (REDG half).
__device__ float g_slices[NSLICE][NN];   /* 10.75 MB */
__device__ float g_val[NN];
__device__ float g_oacc[NOUT];

__device__ __forceinline__ float lrelu(float v) { return v >= 0.f ? v : 0.01f * v; }

// Zero the 32 replica rows + logit accumulator (slices are overwritten each layer).
__global__ void init_kernel() {
    int i = blockIdx.x * blockDim.x + threadIdx.x;      // 256*256 = 65536 float4
    ((float4*)g_slices[LGRID])[i] = make_float4(0.f, 0.f, 0.f, 0.f);
    if (i < NOUT) g_oacc[i] = 0.f;
}

// One hidden layer, hybrid scatter (the only shape measured < 10us):
//   vec0 (58% of edges) -> smem atomics into the CTA-private accumulator
//   vec1 (42% of edges) -> global REDG into 32 replicated accumulators
// The two RMW streams drain on independent back-ends (smem crossbar vs LTS ALUs).
// Epilogue: coalesced non-atomic flush of the smem accumulator to g_slices[bid].
__global__ void __launch_bounds__(512, 2) layer_kernel(
    const int4*   __restrict__ src,
    const int4*   __restrict__ dst,
    const float4* __restrict__ w,
    const float*  __restrict__ vin)
{
    extern __shared__ float smem[];
    float* s_vals = smem;        // [0, 8192)    staged node values
    float* s_acc  = smem + NN;   // [8192,16384) CTA-private accumulator

    const int tid = threadIdx.x;
    const int bid = blockIdx.x;
    const int g   = bid * 512 + tid;          // vec0 index, < GS <= EV
    const int g1  = g + GS;                    // vec1 index, if < EV

    // Prefetch vec0 edges (streaming) before the staging barrier.
    int4   es0 = __ldcs(&src[g]);
    int4   ed0 = __ldcs(&dst[g]);
    float4 ew0 = __ldcs(&w[g]);

    // Stage node values and zero the private accumulator.
    const float4* vin4 = (const float4*)vin;
    float4* s4 = (float4*)s_vals;
    float4* z4 = (float4*)s_acc;
    #pragma unroll
    for (int k = 0; k < 4; ++k) {
        int i = tid + k * 512;
        s4[i] = vin4[i];
        z4[i] = make_float4(0.f, 0.f, 0.f, 0.f);
    }
    __syncthreads();

    // vec0 -> smem atomics (per-CTA private, no cross-CTA contention)
    atomicAdd(&s_acc[ed0.x], s_vals[es0.x] * ew0.x);
    atomicAdd(&s_acc[ed0.y], s_vals[es0.y] * ew0.y);
    atomicAdd(&s_acc[ed0.z], s_vals[es0.z] * ew0.z);
    atomicAdd(&s_acc[ed0.w], s_vals[es0.w] * ew0.w);

    // vec1 -> global REDG into replica (warp, CTA-parity) of the replica window
    if (g1 < EV) {
        int4   es1 = __ldcs(&src[g1]);
        int4   ed1 = __ldcs(&dst[g1]);
        float4 ew1 = __ldcs(&w[g1]);
        float* __restrict__ gout = g_slices[LGRID + (tid >> 5) + ((bid & 1) << 4)];
        atomicAdd(&gout[ed1.x], s_vals[es1.x] * ew1.x);
        atomicAdd(&gout[ed1.y], s_vals[es1.y] * ew1.y);
        atomicAdd(&gout[ed1.z], s_vals[es1.z] * ew1.z);
        atomicAdd(&gout[ed1.w], s_vals[es1.w] * ew1.w);
    }

    __syncthreads();

    // Flush the private accumulator to this CTA's slice (plain coalesced stores).
    float4* slice4 = (float4*)g_slices[bid];
    const float4* a4 = (const float4*)s_acc;
    #pragma unroll
    for (int k = 0; k < 4; ++k) {
        int i = tid + k * 512;
        slice4[i] = a4[i];
    }
}

// WIDE fold: 128 CTAs x 512 threads = 65536 = 2048 float4-columns x 32 slice-groups.
// Each thread sums 10-11 INDEPENDENT float4 loads (L2-resident, ~10.5 MB total),
// re-zeroing replica rows in-pass; smem tree folds the 32 groups; lrelu -> g_val.
// Slice groups: 328 = 8*11 + 24*10.
__global__ void __launch_bounds__(512) reduce_kernel() {
    __shared__ float4 sp[32][16];
    const int tid = threadIdx.x;
    const int c4  = blockIdx.x * 16 + (tid & 15);   // float4 column 0..2047
    const int grp = tid >> 4;                        // 0..31
    const int start = (grp < 8) ? grp * 11 : grp * 10 + 8;
    const int cnt   = (grp < 8) ? 11 : 10;

    float4 s = make_float4(0.f, 0.f, 0.f, 0.f);
    const float4 zero = make_float4(0.f, 0.f, 0.f, 0.f);
    #pragma unroll 11
    for (int k = 0; k < cnt; ++k) {
        int sl = start + k;
        float4 v = ((const float4*)g_slices[sl])[c4];
        if (sl >= LGRID) ((float4*)g_slices[sl])[c4] = zero;   // re-zero replicas
        s.x += v.x; s.y += v.y; s.z += v.z; s.w += v.w;
    }
    sp[grp][tid & 15] = s;
    __syncthreads();

    if (tid < 16) {
        float4 a = make_float4(0.f, 0.f, 0.f, 0.f);
        #pragma unroll
        for (int g2 = 0; g2 < 32; ++g2) {
            float4 v = sp[g2][tid];
            a.x += v.x; a.y += v.y; a.z += v.z; a.w += v.w;
        }
        ((float4*)g_val)[blockIdx.x * 16 + tid] =
            make_float4(lrelu(a.x), lrelu(a.y), lrelu(a.z), lrelu(a.w));
    }
}

// Output layer: 131072 edges into 16 logits. Per-CTA smem bins, one global
// atomic merge per bin per CTA. g_val is already activated.
__global__ void __launch_bounds__(256) out_kernel(
    const int*   __restrict__ osrc,
    const int*   __restrict__ odst,
    const float* __restrict__ ow)
{
    __shared__ float s_acc[NOUT];
    if (threadIdx.x < NOUT) s_acc[threadIdx.x] = 0.f;
    __syncthreads();

    const int g  = blockIdx.x * blockDim.x + threadIdx.x;
    const int gs = gridDim.x * blockDim.x;
    for (int i = g; i < EOUT; i += gs) {
        atomicAdd(&s_acc[odst[i]], g_val[osrc[i]] * ow[i]);
    }
    __syncthreads();
    if (threadIdx.x < NOUT) atomicAdd(&g_oacc[threadIdx.x], s_acc[threadIdx.x]);
}

// lrelu + softmax over the 16 logits; one warp.
__global__ void softmax_kernel(float* __restrict__ out) {
    const int t = threadIdx.x;                  // 32 threads
    float v = (t < NOUT) ? lrelu(g_oacc[t]) : -INFINITY;
    float m = v;
    #pragma unroll
    for (int o = 8; o > 0; o >>= 1) m = fmaxf(m, __shfl_xor_sync(0xffffffffu, m, o));
    float e = (t < NOUT) ? __expf(v - m) : 0.f;
    float s = e;
    #pragma unroll
    for (int o = 8; o > 0; o >>= 1) s += __shfl_xor_sync(0xffffffffu, s, o);
    if (t < NOUT) out[t] = e / s;
}

extern "C" void kernel_launch(void* const* d_in, const int* in_sizes, int n_in,
                              void* d_out, int out_size)
{
    // metadata order: x, edge_w, out_w, edge_src, edge_dst, out_src, out_dst
    const float* x        = (const float*)d_in[0];
    const float* edge_w   = (const float*)d_in[1];
    const float* out_w    = (const float*)d_in[2];
    const int*   edge_src = (const int*)  d_in[3];
    const int*   edge_dst = (const int*)  d_in[4];
    const int*   out_src  = (const int*)  d_in[5];
    const int*   out_dst  = (const int*)  d_in[6];
    float* out = (float*)d_out;

    float* val = nullptr;
    cudaGetSymbolAddress((void**)&val, g_val);   // capture-safe, not a stream op

    // 64 KB dynamic smem opt-in (idempotent, capture-safe).
    cudaFuncSetAttribute(layer_kernel,
                         cudaFuncAttributeMaxDynamicSharedMemorySize, 65536);

    init_kernel<<<256, 256>>>();

    for (int l = 0; l < NL; ++l) {
        const float* vin = (l == 0) ? x : val;
        const size_t off = (size_t)l * NE;
        layer_kernel<<<LGRID, 512, 65536>>>(
            (const int4*)(edge_src + off),
            (const int4*)(edge_dst + off),
            (const float4*)(edge_w + off),
            vin);
        reduce_kernel<<<128, 512>>>();
    }

    out_kernel<<<148, 256>>>(out_src, out_dst, out_w);
    softmax_kernel<<<1, 32>>>(out);
}